// round 12
// baseline (speedup 1.0000x reference)
#include <cuda_runtime.h>
#include <math.h>
#include <float.h>

#define MAXN 512
#define KWAVE 8
#define NSEG 4

// ---------------- fused: prep + tile cull + survivor sort + composite ----------------
// block: (8,16,4) = 512 threads; tile = 8x16 pixels; warp footprint = 8x4
__global__ void __launch_bounds__(512, 3)
fused_kernel(const float* __restrict__ colors,
             const float* __restrict__ opac,
             const float* __restrict__ bg,
             const float* __restrict__ pos,
             const float* __restrict__ scales,
             const float* __restrict__ rots,
             const float* __restrict__ wcoef,
             const int*   __restrict__ widx,
             const float* __restrict__ view,
             const float* __restrict__ VP,
             float* __restrict__ out,
             int N, int W, int H, float fx, float fy)
{
    extern __shared__ float4 dyn[];
    float4* s_rec = dyn;               // [512] px,py,r2,op
    float4* s_f1  = dyn + 512;         // conA,conB,conC,a2x
    float4* s_f2  = dyn + 1024;        // a2y,colR,colG,colB
    float4* s_wc0 = dyn + 1536;
    float4* s_wc1 = dyn + 2048;
    float4* s_wo0 = dyn + 2560;
    float4* s_wo1 = dyn + 3072;        // 57344 B dynamic

    __shared__ float  s_key[MAXN];
    __shared__ float  s_thr[MAXN];     // per-survivor power threshold
    __shared__ int    s_cnt[16];
    __shared__ int    s_total;
    __shared__ float4 s_acc[NSEG][128];   // also sort-val scratch before composite

    int tid  = (threadIdx.z * 16 + threadIdx.y) * 8 + threadIdx.x;
    int warp = tid >> 5;
    int lane = tid & 31;
    float Wf = (float)W, Hf = (float)H;

    // ---------- phase 0: per-thread primitive prep ----------
    float depth = FLT_MAX;
    float thr  = 0.f;
    float4 rec = make_float4(0.f, 0.f, 0.f, 0.f);
    float4 rf1 = make_float4(0.f, 0.f, 0.f, 0.f);
    float4 rf2 = make_float4(0.f, 0.f, 0.f, 0.f);
    float4 rwc0 = rec, rwc1 = rec, rwo0 = rec, rwo1 = rec;

    if (tid < N) {
        int i = tid;
        float4 q4 = __ldg((const float4*)(rots + 4*i));
        float qdot = q4.x*q4.x + q4.y*q4.y + q4.z*q4.z + q4.w*q4.w;
        float qinv = rsqrtf(fmaxf(qdot, 1e-16f));
        float r = q4.x*qinv, x = q4.y*qinv, y = q4.z*qinv, z = q4.w*qinv;
        float R00 = 1.f - 2.f*(y*y + z*z), R01 = 2.f*(x*y - r*z), R02 = 2.f*(x*z + r*y);
        float R10 = 2.f*(x*y + r*z), R11 = 1.f - 2.f*(x*x + z*z), R12 = 2.f*(y*z - r*x);
        float R20 = 2.f*(x*z - r*y), R21 = 2.f*(y*z + r*x), R22 = 1.f - 2.f*(x*x + y*y);

        float sx = __expf(scales[3*i+0]);
        float sy = __expf(scales[3*i+1]);
        float sz = __expf(scales[3*i+2]);
        float s0 = sx*sx, s1 = sy*sy, s2 = sz*sz;

        float p0 = pos[3*i+0], p1 = pos[3*i+1], p2 = pos[3*i+2];

        float tx  = view[0]*p0 + view[1]*p1 + view[2]*p2  + view[3];
        float ty  = view[4]*p0 + view[5]*p1 + view[6]*p2  + view[7];
        float tzc = view[8]*p0 + view[9]*p1 + view[10]*p2 + view[11];

        float c0 = VP[0]*p0  + VP[1]*p1  + VP[2]*p2  + VP[3];
        float c1 = VP[4]*p0  + VP[5]*p1  + VP[6]*p2  + VP[7];
        float w  = VP[12]*p0 + VP[13]*p1 + VP[14]*p2 + VP[15];
        float wsafe = (fabsf(w) > 1e-6f) ? w : 1e-6f;
        float winv = __fdividef(1.0f, wsafe);
        float pxx = (c0*winv * 0.5f + 0.5f) * Wf;
        float pyy = (c1*winv * 0.5f + 0.5f) * Hf;

        depth = tzc;
        float tzm = fmaxf(depth, 0.1f);
        float inv = __fdividef(1.0f, tzm);
        float J00 = fx*inv, J02 = -fx*tx*inv*inv;
        float J11 = fy*inv, J12 = -fy*ty*inv*inv;

        float M00 = J00*view[0] + J02*view[8];
        float M01 = J00*view[1] + J02*view[9];
        float M02 = J00*view[2] + J02*view[10];
        float M10 = J11*view[4] + J12*view[8];
        float M11 = J11*view[5] + J12*view[9];
        float M12 = J11*view[6] + J12*view[10];

        // B = M * R (2x3); cov2d = B * diag(s^2) * B^T; a2 = B[:,0]
        float B00 = M00*R00 + M01*R10 + M02*R20;
        float B01 = M00*R01 + M01*R11 + M02*R21;
        float B02 = M00*R02 + M01*R12 + M02*R22;
        float B10 = M10*R00 + M11*R10 + M12*R20;
        float B11 = M10*R01 + M11*R11 + M12*R21;
        float B12 = M10*R02 + M11*R12 + M12*R22;

        float cov00 = s0*B00*B00 + s1*B01*B01 + s2*B02*B02;
        float cov01 = s0*B00*B10 + s1*B01*B11 + s2*B02*B12;
        float cov11 = s0*B10*B10 + s1*B11*B11 + s2*B12*B12;

        float A = cov00 + 0.3f, B = cov01, C = cov11 + 0.3f;
        float det = fmaxf(A*C - B*B, 1e-12f);
        float invd = __fdividef(1.0f, det);
        float conA = C*invd, conB = -B*invd, conC = A*invd;

        float a2x = B00, a2y = B10;
        float adot = a2x*a2x + a2y*a2y;
        float ainv = rsqrtf(fmaxf(adot, 1e-16f));
        a2x *= ainv; a2y *= ainv;

        float op = opac[i];

        float4 wc0 = __ldg((const float4*)(wcoef + KWAVE*i));
        float4 wc1 = __ldg((const float4*)(wcoef + KWAVE*i) + 1);
        int4   wi0 = __ldg((const int4*)(widx + KWAVE*i));
        int4   wi1 = __ldg((const int4*)(widx + KWAVE*i) + 1);
        float maxw = fabsf(wc0.x)+fabsf(wc0.y)+fabsf(wc0.z)+fabsf(wc0.w)
                   + fabsf(wc1.x)+fabsf(wc1.y)+fabsf(wc1.z)+fabsf(wc1.w);

        bool valid = (depth > 0.1f) && (w > 1e-4f);

        float mean = 0.5f*(conA + conC);
        float disc = fmaxf(0.25f*(conA-conC)*(conA-conC) + conB*conB, 1e-20f);
        float sq   = disc * rsqrtf(disc);      // sqrt(disc)
        float lmin = fmaxf(mean - sq, 1e-12f);
        float r2 = 0.f;
        float prod = op * maxw;
        if (valid && prod > 0.f) {
            float t = __logf(prod) + 18.4207f;   // ln(1e8)
            if (t > 0.f) { thr = t; r2 = __fdividef(2.f * t, lmin); }
        }

        float omc = 0.785398163397448f / Wf;       // (pi/4)/W
        rec  = make_float4(pxx, pyy, r2, op);
        rf1  = make_float4(conA, conB, conC, a2x);
        rf2  = make_float4(a2y, colors[3*i+0], colors[3*i+1], colors[3*i+2]);
        rwc0 = wc0;
        rwc1 = wc1;
        rwo0 = make_float4((float)wi0.x*omc, (float)wi0.y*omc, (float)wi0.z*omc, (float)wi0.w*omc);
        rwo1 = make_float4((float)wi1.x*omc, (float)wi1.y*omc, (float)wi1.z*omc, (float)wi1.w*omc);
    }

    // ---------- phase 1: tile cull + compaction into shared ----------
    float xmin = (float)(blockIdx.x * 8)  + 0.5f;
    float ymin = (float)(blockIdx.y * 16) + 0.5f;
    float xmax = xmin + 7.0f;
    float ymax = ymin + 15.0f;

    float nx = fminf(fmaxf(rec.x, xmin), xmax);
    float ny = fminf(fmaxf(rec.y, ymin), ymax);
    float ddx = rec.x - nx, ddy = rec.y - ny;
    bool p = (ddx*ddx + ddy*ddy) < rec.z;     // r2=0 or invalid -> false

    unsigned msk = __ballot_sync(0xffffffffu, p);
    if (lane == 0) s_cnt[warp] = __popc(msk);
    __syncthreads();

    int pre = 0, run = 0;
    #pragma unroll
    for (int wv = 0; wv < 16; wv++) {
        int c = s_cnt[wv];
        if (wv < warp) pre += c;
        run += c;
    }
    if (tid == 0) s_total = run;

    if (p) {
        int off = pre + __popc(msk & ((1u << lane) - 1));
        s_rec[off] = rec;
        s_f1 [off] = rf1;
        s_f2 [off] = rf2;
        s_wc0[off] = rwc0;
        s_wc1[off] = rwc1;
        s_wo0[off] = rwo0;
        s_wo1[off] = rwo1;
        s_key[off] = depth;
        s_thr[off] = thr;
    }
    __syncthreads();
    int M = s_total;

    // ---------- phase 2: bitonic sort of survivors (only warps < P/32 do work) ----------
    if (M > 1) {
        int P = 1 << (32 - __clz((M > 32 ? M : 32) - 1));   // nextpow2, min 32
        bool sorter = (tid < P);
        int* s_val = (int*)s_acc;
        float key = (tid < M) ? s_key[tid] : FLT_MAX;
        int   val = tid;
        for (int k = 2; k <= P; k <<= 1) {
            bool up = ((tid & k) == 0);
            for (int j = k >> 1; j > 0; j >>= 1) {
                if (j >= 32) {
                    __syncthreads();
                    if (sorter) { s_key[tid] = key; s_val[tid] = val; }
                    __syncthreads();
                    if (sorter) {
                        float okey = s_key[tid ^ j];
                        int   oval = s_val[tid ^ j];
                        bool lower = ((tid & j) == 0);
                        bool takeMin = (lower == up);
                        bool sw = takeMin ? (okey < key) : (okey > key);
                        if (sw) { key = okey; val = oval; }
                    }
                } else if (sorter) {
                    float okey = __shfl_xor_sync(0xffffffffu, key, j);
                    int   oval = __shfl_xor_sync(0xffffffffu, val, j);
                    bool lower = ((tid & j) == 0);
                    bool takeMin = (lower == up);
                    bool sw = takeMin ? (okey < key) : (okey > key);
                    if (sw) { key = okey; val = oval; }
                }
            }
        }
        // permute staged arrays: rank tid takes record from slot val
        __syncthreads();
        float4 pr, p1, p2, pw0, pw1, po0, po1; float pth = 0.f;
        if (tid < M) {
            pr  = s_rec[val];  p1  = s_f1[val];  p2  = s_f2[val];
            pw0 = s_wc0[val];  pw1 = s_wc1[val];
            po0 = s_wo0[val];  po1 = s_wo1[val];
            pth = s_thr[val];
        }
        __syncthreads();
        if (tid < M) {
            s_rec[tid] = pr;  s_f1[tid] = p1;  s_f2[tid] = p2;
            s_wc0[tid] = pw0; s_wc1[tid] = pw1;
            s_wo0[tid] = po0; s_wo1[tid] = po1;
            s_thr[tid] = pth;
        }
        __syncthreads();
    }

    // ---------- phase 3: per-pixel composite over NSEG depth segments ----------
    int x = blockIdx.x * 8  + threadIdx.x;
    int y = blockIdx.y * 16 + threadIdx.y;
    int seg = threadIdx.z;
    float gx = (float)x + 0.5f;
    float gy = (float)y + 0.5f;

    int m0 = (M * seg)       >> 2;
    int m1 = (M * (seg + 1)) >> 2;

    float T = 1.0f, cr = 0.f, cg = 0.f, cb = 0.f;

    for (int m = m0; m < m1; m++) {
        float4 c = s_rec[m];
        float dx = c.x - gx;
        float dy = c.y - gy;
        float d2 = dx*dx + dy*dy;
        if (d2 < c.z) {
            float4 f1 = s_f1[m];
            float power = -0.5f*(f1.x*dx*dx + f1.z*dy*dy) - f1.y*dx*dy;
            // ellipse early-out: skipped => alpha < 1e-8 (same bound as radius cull)
            if (power > -s_thr[m]) {
                float4 f2 = s_f2[m];
                float G = __expf(fminf(power, 0.f));
                float t = dx*f1.w + dy*f2.x;
                float4 wc0 = s_wc0[m];
                float4 wc1 = s_wc1[m];
                float4 wo0 = s_wo0[m];
                float4 wo1 = s_wo1[m];
                float wave = wc0.x*__cosf(wo0.x*t) + wc0.y*__cosf(wo0.y*t)
                           + wc0.z*__cosf(wo0.z*t) + wc0.w*__cosf(wo0.w*t)
                           + wc1.x*__cosf(wo1.x*t) + wc1.y*__cosf(wo1.y*t)
                           + wc1.z*__cosf(wo1.z*t) + wc1.w*__cosf(wo1.w*t);
                float alpha = fminf(fmaxf(c.w * G * wave, 0.f), 0.99f);
                float wgt = alpha * T;
                cr += wgt * f2.y;
                cg += wgt * f2.z;
                cb += wgt * f2.w;
                T *= 1.0f - alpha;
            }
        }
    }

    int pixl = threadIdx.y * 8 + threadIdx.x;
    __syncthreads();                     // s_acc (sort scratch) is dead
    s_acc[seg][pixl] = make_float4(cr, cg, cb, T);
    __syncthreads();

    if (seg == 0 && x < W && y < H) {
        float fr = 0.f, fg = 0.f, fb = 0.f, fT = 1.f;
        #pragma unroll
        for (int sgi = NSEG - 1; sgi >= 0; sgi--) {
            float4 a = s_acc[sgi][pixl];
            fr = a.x + a.w * fr;
            fg = a.y + a.w * fg;
            fb = a.z + a.w * fb;
            fT *= a.w;
        }
        int pix = y*W + x;
        int HW = W*H;
        out[pix]        = fr + bg[0]*fT;
        out[HW + pix]   = fg + bg[1]*fT;
        out[2*HW + pix] = fb + bg[2]*fT;
    }
}

// ---------------- launch ----------------
extern "C" void kernel_launch(void* const* d_in, const int* in_sizes, int n_in,
                              void* d_out, int out_size)
{
    const float* colors = (const float*)d_in[0];
    const float* opac   = (const float*)d_in[1];
    const float* bg     = (const float*)d_in[2];
    const float* pos    = (const float*)d_in[3];
    const float* scales = (const float*)d_in[4];
    const float* rots   = (const float*)d_in[5];
    const float* wcoef  = (const float*)d_in[6];
    const int*   widx   = (const int*)d_in[7];
    const float* view   = (const float*)d_in[9];
    const float* VP     = (const float*)d_in[10];

    int N = in_sizes[3] / 3;
    if (N > MAXN) N = MAXN;

    int HW = out_size / 3;
    int W = 200, H = 200;
    if (HW != 40000) {
        W = (int)(sqrt((double)HW) + 0.5);
        H = (W > 0) ? HW / W : 0;
    }

    const double tanx = tan(30.0 * M_PI / 180.0);  // FOV 60 deg
    const double tany = tan(30.0 * M_PI / 180.0);
    float fx = (float)(W / (2.0 * tanx));
    float fy = (float)(H / (2.0 * tany));

    const int dyn_bytes = 3584 * 16;   // 57344
    cudaFuncSetAttribute(fused_kernel,
                         cudaFuncAttributeMaxDynamicSharedMemorySize, dyn_bytes);

    dim3 blk(8, 16, NSEG);
    dim3 grd((W + 7) / 8, (H + 15) / 16);
    fused_kernel<<<grd, blk, dyn_bytes>>>(colors, opac, bg, pos, scales, rots,
                                          wcoef, widx, view, VP,
                                          (float*)d_out, N, W, H, fx, fy);
}

// round 13
// speedup vs baseline: 1.1348x; 1.1348x over previous
#include <cuda_runtime.h>
#include <math.h>
#include <float.h>

#define MAXN 512
#define KWAVE 8
#define NSEG 4

// ---------------- fused: prep + tile cull + survivor sort + composite ----------------
// block: (8,16,4) = 512 threads; tile = 8x16 pixels; warp footprint = 8x4
__global__ void __launch_bounds__(512, 3)
fused_kernel(const float* __restrict__ colors,
             const float* __restrict__ opac,
             const float* __restrict__ bg,
             const float* __restrict__ pos,
             const float* __restrict__ scales,
             const float* __restrict__ rots,
             const float* __restrict__ wcoef,
             const int*   __restrict__ widx,
             const float* __restrict__ view,
             const float* __restrict__ VP,
             float* __restrict__ out,
             int N, int W, int H, float fx, float fy)
{
    extern __shared__ float4 dyn[];
    float4* s_rec = dyn;               // [512] px,py,r2,thr
    float4* s_f1  = dyn + 512;         // conA,conB,conC,a2x
    float4* s_f2  = dyn + 1024;        // a2y,colR,colG,colB
    float4* s_wc0 = dyn + 1536;        // op-folded wave coeffs 0..3
    float4* s_wc1 = dyn + 2048;        // op-folded wave coeffs 4..7
    float4* s_wo0 = dyn + 2560;
    float4* s_wo1 = dyn + 3072;        // 57344 B dynamic

    __shared__ float  s_key[MAXN];
    __shared__ int    s_cnt[16];
    __shared__ int    s_total;
    __shared__ float4 s_acc[NSEG][128];   // also sort-val scratch before composite

    int tid  = (threadIdx.z * 16 + threadIdx.y) * 8 + threadIdx.x;
    int warp = tid >> 5;
    int lane = tid & 31;
    float Wf = (float)W, Hf = (float)H;

    // ---------- phase 0: per-thread primitive prep ----------
    float depth = FLT_MAX;
    float4 rec = make_float4(0.f, 0.f, 0.f, 0.f);
    float4 rf1 = make_float4(0.f, 0.f, 0.f, 0.f);
    float4 rf2 = make_float4(0.f, 0.f, 0.f, 0.f);
    float4 rwc0 = rec, rwc1 = rec, rwo0 = rec, rwo1 = rec;

    if (tid < N) {
        int i = tid;
        float4 q4 = __ldg((const float4*)(rots + 4*i));
        float qdot = q4.x*q4.x + q4.y*q4.y + q4.z*q4.z + q4.w*q4.w;
        float qinv = rsqrtf(fmaxf(qdot, 1e-16f));
        float r = q4.x*qinv, x = q4.y*qinv, y = q4.z*qinv, z = q4.w*qinv;
        float R00 = 1.f - 2.f*(y*y + z*z), R01 = 2.f*(x*y - r*z), R02 = 2.f*(x*z + r*y);
        float R10 = 2.f*(x*y + r*z), R11 = 1.f - 2.f*(x*x + z*z), R12 = 2.f*(y*z - r*x);
        float R20 = 2.f*(x*z - r*y), R21 = 2.f*(y*z + r*x), R22 = 1.f - 2.f*(x*x + y*y);

        float sx = __expf(scales[3*i+0]);
        float sy = __expf(scales[3*i+1]);
        float sz = __expf(scales[3*i+2]);
        float s0 = sx*sx, s1 = sy*sy, s2 = sz*sz;

        float p0 = pos[3*i+0], p1 = pos[3*i+1], p2 = pos[3*i+2];

        float tx  = view[0]*p0 + view[1]*p1 + view[2]*p2  + view[3];
        float ty  = view[4]*p0 + view[5]*p1 + view[6]*p2  + view[7];
        float tzc = view[8]*p0 + view[9]*p1 + view[10]*p2 + view[11];

        float c0 = VP[0]*p0  + VP[1]*p1  + VP[2]*p2  + VP[3];
        float c1 = VP[4]*p0  + VP[5]*p1  + VP[6]*p2  + VP[7];
        float w  = VP[12]*p0 + VP[13]*p1 + VP[14]*p2 + VP[15];
        float wsafe = (fabsf(w) > 1e-6f) ? w : 1e-6f;
        float winv = __fdividef(1.0f, wsafe);
        float pxx = (c0*winv * 0.5f + 0.5f) * Wf;
        float pyy = (c1*winv * 0.5f + 0.5f) * Hf;

        depth = tzc;
        float tzm = fmaxf(depth, 0.1f);
        float inv = __fdividef(1.0f, tzm);
        float J00 = fx*inv, J02 = -fx*tx*inv*inv;
        float J11 = fy*inv, J12 = -fy*ty*inv*inv;

        float M00 = J00*view[0] + J02*view[8];
        float M01 = J00*view[1] + J02*view[9];
        float M02 = J00*view[2] + J02*view[10];
        float M10 = J11*view[4] + J12*view[8];
        float M11 = J11*view[5] + J12*view[9];
        float M12 = J11*view[6] + J12*view[10];

        // B = M * R (2x3); cov2d = B * diag(s^2) * B^T; a2 = B[:,0]
        float B00 = M00*R00 + M01*R10 + M02*R20;
        float B01 = M00*R01 + M01*R11 + M02*R21;
        float B02 = M00*R02 + M01*R12 + M02*R22;
        float B10 = M10*R00 + M11*R10 + M12*R20;
        float B11 = M10*R01 + M11*R11 + M12*R21;
        float B12 = M10*R02 + M11*R12 + M12*R22;

        float cov00 = s0*B00*B00 + s1*B01*B01 + s2*B02*B02;
        float cov01 = s0*B00*B10 + s1*B01*B11 + s2*B02*B12;
        float cov11 = s0*B10*B10 + s1*B11*B11 + s2*B12*B12;

        float A = cov00 + 0.3f, B = cov01, C = cov11 + 0.3f;
        float det = fmaxf(A*C - B*B, 1e-12f);
        float invd = __fdividef(1.0f, det);
        float conA = C*invd, conB = -B*invd, conC = A*invd;

        float a2x = B00, a2y = B10;
        float adot = a2x*a2x + a2y*a2y;
        float ainv = rsqrtf(fmaxf(adot, 1e-16f));
        a2x *= ainv; a2y *= ainv;

        float op = opac[i];

        float4 wc0 = __ldg((const float4*)(wcoef + KWAVE*i));
        float4 wc1 = __ldg((const float4*)(wcoef + KWAVE*i) + 1);
        int4   wi0 = __ldg((const int4*)(widx + KWAVE*i));
        int4   wi1 = __ldg((const int4*)(widx + KWAVE*i) + 1);
        float maxw = fabsf(wc0.x)+fabsf(wc0.y)+fabsf(wc0.z)+fabsf(wc0.w)
                   + fabsf(wc1.x)+fabsf(wc1.y)+fabsf(wc1.z)+fabsf(wc1.w);

        bool valid = (depth > 0.1f) && (w > 1e-4f);

        float mean = 0.5f*(conA + conC);
        float disc = fmaxf(0.25f*(conA-conC)*(conA-conC) + conB*conB, 1e-20f);
        float sq   = disc * rsqrtf(disc);      // sqrt(disc)
        float lmin = fmaxf(mean - sq, 1e-12f);
        float thr = 0.f, r2 = 0.f;
        float prod = op * maxw;
        if (valid && prod > 0.f) {
            float t = __logf(prod) + 13.8155f;   // ln(1e6): skipped alpha < 1e-6
            if (t > 0.f) { thr = t; r2 = __fdividef(2.f * t, lmin); }
        }

        float omc = 0.785398163397448f / Wf;       // (pi/4)/W
        rec  = make_float4(pxx, pyy, r2, thr);
        rf1  = make_float4(conA, conB, conC, a2x);
        rf2  = make_float4(a2y, colors[3*i+0], colors[3*i+1], colors[3*i+2]);
        // fold opacity into wave coefficients: alpha = G * sum(op*ck*cos(...))
        rwc0 = make_float4(op*wc0.x, op*wc0.y, op*wc0.z, op*wc0.w);
        rwc1 = make_float4(op*wc1.x, op*wc1.y, op*wc1.z, op*wc1.w);
        rwo0 = make_float4((float)wi0.x*omc, (float)wi0.y*omc, (float)wi0.z*omc, (float)wi0.w*omc);
        rwo1 = make_float4((float)wi1.x*omc, (float)wi1.y*omc, (float)wi1.z*omc, (float)wi1.w*omc);
    }

    // ---------- phase 1: tile cull + compaction into shared ----------
    float xmin = (float)(blockIdx.x * 8)  + 0.5f;
    float ymin = (float)(blockIdx.y * 16) + 0.5f;
    float xmax = xmin + 7.0f;
    float ymax = ymin + 15.0f;

    float nx = fminf(fmaxf(rec.x, xmin), xmax);
    float ny = fminf(fmaxf(rec.y, ymin), ymax);
    float ddx = rec.x - nx, ddy = rec.y - ny;
    bool p = (ddx*ddx + ddy*ddy) < rec.z;     // r2=0 or invalid -> false

    unsigned msk = __ballot_sync(0xffffffffu, p);
    if (lane == 0) s_cnt[warp] = __popc(msk);
    __syncthreads();

    int pre = 0, run = 0;
    #pragma unroll
    for (int wv = 0; wv < 16; wv++) {
        int c = s_cnt[wv];
        if (wv < warp) pre += c;
        run += c;
    }
    if (tid == 0) s_total = run;

    if (p) {
        int off = pre + __popc(msk & ((1u << lane) - 1));
        s_rec[off] = rec;
        s_f1 [off] = rf1;
        s_f2 [off] = rf2;
        s_wc0[off] = rwc0;
        s_wc1[off] = rwc1;
        s_wo0[off] = rwo0;
        s_wo1[off] = rwo1;
        s_key[off] = depth;
    }
    __syncthreads();
    int M = s_total;

    // ---------- phase 2: bitonic sort of survivors (only warps < P/32 do work) ----------
    if (M > 1) {
        int P = 1 << (32 - __clz((M > 32 ? M : 32) - 1));   // nextpow2, min 32
        bool sorter = (tid < P);
        int* s_val = (int*)s_acc;
        float key = (tid < M) ? s_key[tid] : FLT_MAX;
        int   val = tid;
        for (int k = 2; k <= P; k <<= 1) {
            bool up = ((tid & k) == 0);
            for (int j = k >> 1; j > 0; j >>= 1) {
                if (j >= 32) {
                    __syncthreads();
                    if (sorter) { s_key[tid] = key; s_val[tid] = val; }
                    __syncthreads();
                    if (sorter) {
                        float okey = s_key[tid ^ j];
                        int   oval = s_val[tid ^ j];
                        bool lower = ((tid & j) == 0);
                        bool takeMin = (lower == up);
                        bool sw = takeMin ? (okey < key) : (okey > key);
                        if (sw) { key = okey; val = oval; }
                    }
                } else if (sorter) {
                    float okey = __shfl_xor_sync(0xffffffffu, key, j);
                    int   oval = __shfl_xor_sync(0xffffffffu, val, j);
                    bool lower = ((tid & j) == 0);
                    bool takeMin = (lower == up);
                    bool sw = takeMin ? (okey < key) : (okey > key);
                    if (sw) { key = okey; val = oval; }
                }
            }
        }
        // permute staged arrays: rank tid takes record from slot val
        __syncthreads();
        float4 pr, p1, p2, pw0, pw1, po0, po1;
        if (tid < M) {
            pr  = s_rec[val];  p1  = s_f1[val];  p2  = s_f2[val];
            pw0 = s_wc0[val];  pw1 = s_wc1[val];
            po0 = s_wo0[val];  po1 = s_wo1[val];
        }
        __syncthreads();
        if (tid < M) {
            s_rec[tid] = pr;  s_f1[tid] = p1;  s_f2[tid] = p2;
            s_wc0[tid] = pw0; s_wc1[tid] = pw1;
            s_wo0[tid] = po0; s_wo1[tid] = po1;
        }
        __syncthreads();
    }

    // ---------- phase 3: per-pixel composite over NSEG depth segments ----------
    int x = blockIdx.x * 8  + threadIdx.x;
    int y = blockIdx.y * 16 + threadIdx.y;
    int seg = threadIdx.z;
    float gx = (float)x + 0.5f;
    float gy = (float)y + 0.5f;

    int m0 = (M * seg)       >> 2;
    int m1 = (M * (seg + 1)) >> 2;

    float T = 1.0f, cr = 0.f, cg = 0.f, cb = 0.f;

    #pragma unroll 2
    for (int m = m0; m < m1; m++) {
        float4 c = s_rec[m];
        float dx = c.x - gx;
        float dy = c.y - gy;
        float d2 = dx*dx + dy*dy;
        if (d2 < c.z) {
            float4 f1 = s_f1[m];
            float power = -0.5f*(f1.x*dx*dx + f1.z*dy*dy) - f1.y*dx*dy;
            // ellipse early-out: skipped => alpha < 1e-6 (same bound as radius cull)
            if (power > -c.w) {
                float4 f2 = s_f2[m];
                float G = __expf(power);       // power <= 0 (conic PSD)
                float t = dx*f1.w + dy*f2.x;
                float4 wc0 = s_wc0[m];
                float4 wc1 = s_wc1[m];
                float4 wo0 = s_wo0[m];
                float4 wo1 = s_wo1[m];
                float wave = wc0.x*__cosf(wo0.x*t) + wc0.y*__cosf(wo0.y*t)
                           + wc0.z*__cosf(wo0.z*t) + wc0.w*__cosf(wo0.w*t)
                           + wc1.x*__cosf(wo1.x*t) + wc1.y*__cosf(wo1.y*t)
                           + wc1.z*__cosf(wo1.z*t) + wc1.w*__cosf(wo1.w*t);
                float alpha = fminf(fmaxf(G * wave, 0.f), 0.99f);
                float wgt = alpha * T;
                cr += wgt * f2.y;
                cg += wgt * f2.z;
                cb += wgt * f2.w;
                T *= 1.0f - alpha;
            }
        }
    }

    int pixl = threadIdx.y * 8 + threadIdx.x;
    __syncthreads();                     // s_acc (sort scratch) is dead
    s_acc[seg][pixl] = make_float4(cr, cg, cb, T);
    __syncthreads();

    if (seg == 0 && x < W && y < H) {
        float fr = 0.f, fg = 0.f, fb = 0.f, fT = 1.f;
        #pragma unroll
        for (int sgi = NSEG - 1; sgi >= 0; sgi--) {
            float4 a = s_acc[sgi][pixl];
            fr = a.x + a.w * fr;
            fg = a.y + a.w * fg;
            fb = a.z + a.w * fb;
            fT *= a.w;
        }
        int pix = y*W + x;
        int HW = W*H;
        out[pix]        = fr + bg[0]*fT;
        out[HW + pix]   = fg + bg[1]*fT;
        out[2*HW + pix] = fb + bg[2]*fT;
    }
}

// ---------------- launch ----------------
extern "C" void kernel_launch(void* const* d_in, const int* in_sizes, int n_in,
                              void* d_out, int out_size)
{
    const float* colors = (const float*)d_in[0];
    const float* opac   = (const float*)d_in[1];
    const float* bg     = (const float*)d_in[2];
    const float* pos    = (const float*)d_in[3];
    const float* scales = (const float*)d_in[4];
    const float* rots   = (const float*)d_in[5];
    const float* wcoef  = (const float*)d_in[6];
    const int*   widx   = (const int*)d_in[7];
    const float* view   = (const float*)d_in[9];
    const float* VP     = (const float*)d_in[10];

    int N = in_sizes[3] / 3;
    if (N > MAXN) N = MAXN;

    int HW = out_size / 3;
    int W = 200, H = 200;
    if (HW != 40000) {
        W = (int)(sqrt((double)HW) + 0.5);
        H = (W > 0) ? HW / W : 0;
    }

    const double tanx = tan(30.0 * M_PI / 180.0);  // FOV 60 deg
    const double tany = tan(30.0 * M_PI / 180.0);
    float fx = (float)(W / (2.0 * tanx));
    float fy = (float)(H / (2.0 * tany));

    const int dyn_bytes = 3584 * 16;   // 57344
    cudaFuncSetAttribute(fused_kernel,
                         cudaFuncAttributeMaxDynamicSharedMemorySize, dyn_bytes);

    dim3 blk(8, 16, NSEG);
    dim3 grd((W + 7) / 8, (H + 15) / 16);
    fused_kernel<<<grd, blk, dyn_bytes>>>(colors, opac, bg, pos, scales, rots,
                                          wcoef, widx, view, VP,
                                          (float*)d_out, N, W, H, fx, fy);
}

// round 14
// speedup vs baseline: 1.1604x; 1.0226x over previous
#include <cuda_runtime.h>
#include <math.h>
#include <float.h>

#define MAXN 512
#define KWAVE 8
#define NSEG 4

// ---------------- fused: prep + tile cull + survivor sort + composite ----------------
// block: (8,16,4) = 512 threads; tile = 8x16 pixels; warp footprint = 8x4
__global__ void __launch_bounds__(512, 3)
fused_kernel(const float* __restrict__ colors,
             const float* __restrict__ opac,
             const float* __restrict__ bg,
             const float* __restrict__ pos,
             const float* __restrict__ scales,
             const float* __restrict__ rots,
             const float* __restrict__ wcoef,
             const int*   __restrict__ widx,
             const float* __restrict__ view,
             const float* __restrict__ VP,
             float* __restrict__ out,
             int N, int W, int H, float fx, float fy)
{
    extern __shared__ float4 dyn[];
    float4* s_rec = dyn;               // [512] px,py,r2,thr
    float4* s_f1  = dyn + 512;         // conA,conB,conC,a2x
    float4* s_f2  = dyn + 1024;        // a2y,colR,colG,colB
    float4* s_wc0 = dyn + 1536;        // op-folded wave coeffs 0..3
    float4* s_wc1 = dyn + 2048;        // op-folded wave coeffs 4..7
    float4* s_wo0 = dyn + 2560;
    float4* s_wo1 = dyn + 3072;        // 57344 B dynamic

    __shared__ float  s_key[MAXN];
    __shared__ int    s_cnt[16];
    __shared__ int    s_total;
    __shared__ float4 s_acc[NSEG][128];   // also sort-val scratch before composite

    int tid  = (threadIdx.z * 16 + threadIdx.y) * 8 + threadIdx.x;
    int warp = tid >> 5;
    int lane = tid & 31;
    float Wf = (float)W, Hf = (float)H;

    // ---------- phase 0: per-thread primitive prep ----------
    float depth = FLT_MAX;
    float4 rec = make_float4(0.f, 0.f, 0.f, 0.f);
    float4 rf1 = make_float4(0.f, 0.f, 0.f, 0.f);
    float4 rf2 = make_float4(0.f, 0.f, 0.f, 0.f);
    float4 rwc0 = rec, rwc1 = rec, rwo0 = rec, rwo1 = rec;

    if (tid < N) {
        int i = tid;
        float4 q4 = __ldg((const float4*)(rots + 4*i));
        float qdot = q4.x*q4.x + q4.y*q4.y + q4.z*q4.z + q4.w*q4.w;
        float qinv = rsqrtf(fmaxf(qdot, 1e-16f));
        float r = q4.x*qinv, x = q4.y*qinv, y = q4.z*qinv, z = q4.w*qinv;
        float R00 = 1.f - 2.f*(y*y + z*z), R01 = 2.f*(x*y - r*z), R02 = 2.f*(x*z + r*y);
        float R10 = 2.f*(x*y + r*z), R11 = 1.f - 2.f*(x*x + z*z), R12 = 2.f*(y*z - r*x);
        float R20 = 2.f*(x*z - r*y), R21 = 2.f*(y*z + r*x), R22 = 1.f - 2.f*(x*x + y*y);

        float sx = __expf(scales[3*i+0]);
        float sy = __expf(scales[3*i+1]);
        float sz = __expf(scales[3*i+2]);
        float s0 = sx*sx, s1 = sy*sy, s2 = sz*sz;

        float p0 = pos[3*i+0], p1 = pos[3*i+1], p2 = pos[3*i+2];

        float tx  = view[0]*p0 + view[1]*p1 + view[2]*p2  + view[3];
        float ty  = view[4]*p0 + view[5]*p1 + view[6]*p2  + view[7];
        float tzc = view[8]*p0 + view[9]*p1 + view[10]*p2 + view[11];

        float c0 = VP[0]*p0  + VP[1]*p1  + VP[2]*p2  + VP[3];
        float c1 = VP[4]*p0  + VP[5]*p1  + VP[6]*p2  + VP[7];
        float w  = VP[12]*p0 + VP[13]*p1 + VP[14]*p2 + VP[15];
        float wsafe = (fabsf(w) > 1e-6f) ? w : 1e-6f;
        float winv = __fdividef(1.0f, wsafe);
        float pxx = (c0*winv * 0.5f + 0.5f) * Wf;
        float pyy = (c1*winv * 0.5f + 0.5f) * Hf;

        depth = tzc;
        float tzm = fmaxf(depth, 0.1f);
        float inv = __fdividef(1.0f, tzm);
        float J00 = fx*inv, J02 = -fx*tx*inv*inv;
        float J11 = fy*inv, J12 = -fy*ty*inv*inv;

        float M00 = J00*view[0] + J02*view[8];
        float M01 = J00*view[1] + J02*view[9];
        float M02 = J00*view[2] + J02*view[10];
        float M10 = J11*view[4] + J12*view[8];
        float M11 = J11*view[5] + J12*view[9];
        float M12 = J11*view[6] + J12*view[10];

        // B = M * R (2x3); cov2d = B * diag(s^2) * B^T; a2 = B[:,0]
        float B00 = M00*R00 + M01*R10 + M02*R20;
        float B01 = M00*R01 + M01*R11 + M02*R21;
        float B02 = M00*R02 + M01*R12 + M02*R22;
        float B10 = M10*R00 + M11*R10 + M12*R20;
        float B11 = M10*R01 + M11*R11 + M12*R21;
        float B12 = M10*R02 + M11*R12 + M12*R22;

        float cov00 = s0*B00*B00 + s1*B01*B01 + s2*B02*B02;
        float cov01 = s0*B00*B10 + s1*B01*B11 + s2*B02*B12;
        float cov11 = s0*B10*B10 + s1*B11*B11 + s2*B12*B12;

        float A = cov00 + 0.3f, B = cov01, C = cov11 + 0.3f;
        float det = fmaxf(A*C - B*B, 1e-12f);
        float invd = __fdividef(1.0f, det);
        float conA = C*invd, conB = -B*invd, conC = A*invd;

        float a2x = B00, a2y = B10;
        float adot = a2x*a2x + a2y*a2y;
        float ainv = rsqrtf(fmaxf(adot, 1e-16f));
        a2x *= ainv; a2y *= ainv;

        float op = opac[i];

        float4 wc0 = __ldg((const float4*)(wcoef + KWAVE*i));
        float4 wc1 = __ldg((const float4*)(wcoef + KWAVE*i) + 1);
        int4   wi0 = __ldg((const int4*)(widx + KWAVE*i));
        int4   wi1 = __ldg((const int4*)(widx + KWAVE*i) + 1);
        float maxw = fabsf(wc0.x)+fabsf(wc0.y)+fabsf(wc0.z)+fabsf(wc0.w)
                   + fabsf(wc1.x)+fabsf(wc1.y)+fabsf(wc1.z)+fabsf(wc1.w);

        bool valid = (depth > 0.1f) && (w > 1e-4f);

        float mean = 0.5f*(conA + conC);
        float disc = fmaxf(0.25f*(conA-conC)*(conA-conC) + conB*conB, 1e-20f);
        float sq   = disc * rsqrtf(disc);      // sqrt(disc)
        float lmin = fmaxf(mean - sq, 1e-12f);
        float thr = 0.f, r2 = 0.f;
        float prod = op * maxw;
        if (valid && prod > 0.f) {
            float t = __logf(prod) + 11.5129f;   // ln(1e5): skipped alpha < 1e-5
            if (t > 0.f) { thr = t; r2 = __fdividef(2.f * t, lmin); }
        }

        float omc = 0.785398163397448f / Wf;       // (pi/4)/W
        rec  = make_float4(pxx, pyy, r2, thr);
        rf1  = make_float4(conA, conB, conC, a2x);
        rf2  = make_float4(a2y, colors[3*i+0], colors[3*i+1], colors[3*i+2]);
        // fold opacity into wave coefficients: alpha = G * sum(op*ck*cos(...))
        rwc0 = make_float4(op*wc0.x, op*wc0.y, op*wc0.z, op*wc0.w);
        rwc1 = make_float4(op*wc1.x, op*wc1.y, op*wc1.z, op*wc1.w);
        rwo0 = make_float4((float)wi0.x*omc, (float)wi0.y*omc, (float)wi0.z*omc, (float)wi0.w*omc);
        rwo1 = make_float4((float)wi1.x*omc, (float)wi1.y*omc, (float)wi1.z*omc, (float)wi1.w*omc);
    }

    // ---------- phase 1: tile cull + compaction into shared ----------
    float xmin = (float)(blockIdx.x * 8)  + 0.5f;
    float ymin = (float)(blockIdx.y * 16) + 0.5f;
    float xmax = xmin + 7.0f;
    float ymax = ymin + 15.0f;

    float nx = fminf(fmaxf(rec.x, xmin), xmax);
    float ny = fminf(fmaxf(rec.y, ymin), ymax);
    float ddx = rec.x - nx, ddy = rec.y - ny;
    bool p = (ddx*ddx + ddy*ddy) < rec.z;     // r2=0 or invalid -> false

    unsigned msk = __ballot_sync(0xffffffffu, p);
    if (lane == 0) s_cnt[warp] = __popc(msk);
    __syncthreads();

    int pre = 0, run = 0;
    #pragma unroll
    for (int wv = 0; wv < 16; wv++) {
        int c = s_cnt[wv];
        if (wv < warp) pre += c;
        run += c;
    }
    if (tid == 0) s_total = run;

    if (p) {
        int off = pre + __popc(msk & ((1u << lane) - 1));
        s_rec[off] = rec;
        s_f1 [off] = rf1;
        s_f2 [off] = rf2;
        s_wc0[off] = rwc0;
        s_wc1[off] = rwc1;
        s_wo0[off] = rwo0;
        s_wo1[off] = rwo1;
        s_key[off] = depth;
    }
    __syncthreads();
    int M = s_total;

    // ---------- phase 2: bitonic sort of survivors (only warps < P/32 do work) ----------
    if (M > 1) {
        int P = 1 << (32 - __clz((M > 32 ? M : 32) - 1));   // nextpow2, min 32
        bool sorter = (tid < P);
        int* s_val = (int*)s_acc;
        float key = (tid < M) ? s_key[tid] : FLT_MAX;
        int   val = tid;
        for (int k = 2; k <= P; k <<= 1) {
            bool up = ((tid & k) == 0);
            for (int j = k >> 1; j > 0; j >>= 1) {
                if (j >= 32) {
                    __syncthreads();
                    if (sorter) { s_key[tid] = key; s_val[tid] = val; }
                    __syncthreads();
                    if (sorter) {
                        float okey = s_key[tid ^ j];
                        int   oval = s_val[tid ^ j];
                        bool lower = ((tid & j) == 0);
                        bool takeMin = (lower == up);
                        bool sw = takeMin ? (okey < key) : (okey > key);
                        if (sw) { key = okey; val = oval; }
                    }
                } else if (sorter) {
                    float okey = __shfl_xor_sync(0xffffffffu, key, j);
                    int   oval = __shfl_xor_sync(0xffffffffu, val, j);
                    bool lower = ((tid & j) == 0);
                    bool takeMin = (lower == up);
                    bool sw = takeMin ? (okey < key) : (okey > key);
                    if (sw) { key = okey; val = oval; }
                }
            }
        }
        // permute staged arrays: rank tid takes record from slot val
        __syncthreads();
        float4 pr, p1, p2, pw0, pw1, po0, po1;
        if (tid < M) {
            pr  = s_rec[val];  p1  = s_f1[val];  p2  = s_f2[val];
            pw0 = s_wc0[val];  pw1 = s_wc1[val];
            po0 = s_wo0[val];  po1 = s_wo1[val];
        }
        __syncthreads();
        if (tid < M) {
            s_rec[tid] = pr;  s_f1[tid] = p1;  s_f2[tid] = p2;
            s_wc0[tid] = pw0; s_wc1[tid] = pw1;
            s_wo0[tid] = po0; s_wo1[tid] = po1;
        }
        __syncthreads();
    }

    // ---------- phase 3: per-pixel composite over NSEG depth segments ----------
    int x = blockIdx.x * 8  + threadIdx.x;
    int y = blockIdx.y * 16 + threadIdx.y;
    int seg = threadIdx.z;
    float gx = (float)x + 0.5f;
    float gy = (float)y + 0.5f;

    int m0 = (M * seg)       >> 2;
    int m1 = (M * (seg + 1)) >> 2;

    float T = 1.0f, cr = 0.f, cg = 0.f, cb = 0.f;

    #pragma unroll 2
    for (int m = m0; m < m1; m++) {
        float4 c = s_rec[m];
        float dx = c.x - gx;
        float dy = c.y - gy;
        float d2 = dx*dx + dy*dy;
        if (d2 < c.z) {
            float4 f1 = s_f1[m];
            float power = -0.5f*(f1.x*dx*dx + f1.z*dy*dy) - f1.y*dx*dy;
            // ellipse early-out: skipped => alpha < 1e-5 (same bound as radius cull)
            if (power > -c.w) {
                float4 f2 = s_f2[m];
                float G = __expf(power);       // power <= 0 (conic PSD)
                float t = dx*f1.w + dy*f2.x;
                float4 wc0 = s_wc0[m];
                float4 wc1 = s_wc1[m];
                float4 wo0 = s_wo0[m];
                float4 wo1 = s_wo1[m];
                float wave = wc0.x*__cosf(wo0.x*t) + wc0.y*__cosf(wo0.y*t)
                           + wc0.z*__cosf(wo0.z*t) + wc0.w*__cosf(wo0.w*t)
                           + wc1.x*__cosf(wo1.x*t) + wc1.y*__cosf(wo1.y*t)
                           + wc1.z*__cosf(wo1.z*t) + wc1.w*__cosf(wo1.w*t);
                float alpha = fminf(fmaxf(G * wave, 0.f), 0.99f);
                float wgt = alpha * T;
                cr += wgt * f2.y;
                cg += wgt * f2.z;
                cb += wgt * f2.w;
                T *= 1.0f - alpha;
            }
        }
    }

    int pixl = threadIdx.y * 8 + threadIdx.x;
    __syncthreads();                     // s_acc (sort scratch) is dead
    s_acc[seg][pixl] = make_float4(cr, cg, cb, T);
    __syncthreads();

    if (seg == 0 && x < W && y < H) {
        float fr = 0.f, fg = 0.f, fb = 0.f, fT = 1.f;
        #pragma unroll
        for (int sgi = NSEG - 1; sgi >= 0; sgi--) {
            float4 a = s_acc[sgi][pixl];
            fr = a.x + a.w * fr;
            fg = a.y + a.w * fg;
            fb = a.z + a.w * fb;
            fT *= a.w;
        }
        int pix = y*W + x;
        int HW = W*H;
        out[pix]        = fr + bg[0]*fT;
        out[HW + pix]   = fg + bg[1]*fT;
        out[2*HW + pix] = fb + bg[2]*fT;
    }
}

// ---------------- launch ----------------
extern "C" void kernel_launch(void* const* d_in, const int* in_sizes, int n_in,
                              void* d_out, int out_size)
{
    const float* colors = (const float*)d_in[0];
    const float* opac   = (const float*)d_in[1];
    const float* bg     = (const float*)d_in[2];
    const float* pos    = (const float*)d_in[3];
    const float* scales = (const float*)d_in[4];
    const float* rots   = (const float*)d_in[5];
    const float* wcoef  = (const float*)d_in[6];
    const int*   widx   = (const int*)d_in[7];
    const float* view   = (const float*)d_in[9];
    const float* VP     = (const float*)d_in[10];

    int N = in_sizes[3] / 3;
    if (N > MAXN) N = MAXN;

    int HW = out_size / 3;
    int W = 200, H = 200;
    if (HW != 40000) {
        W = (int)(sqrt((double)HW) + 0.5);
        H = (W > 0) ? HW / W : 0;
    }

    const double tanx = tan(30.0 * M_PI / 180.0);  // FOV 60 deg
    const double tany = tan(30.0 * M_PI / 180.0);
    float fx = (float)(W / (2.0 * tanx));
    float fy = (float)(H / (2.0 * tany));

    const int dyn_bytes = 3584 * 16;   // 57344
    cudaFuncSetAttribute(fused_kernel,
                         cudaFuncAttributeMaxDynamicSharedMemorySize, dyn_bytes);

    dim3 blk(8, 16, NSEG);
    dim3 grd((W + 7) / 8, (H + 15) / 16);
    fused_kernel<<<grd, blk, dyn_bytes>>>(colors, opac, bg, pos, scales, rots,
                                          wcoef, widx, view, VP,
                                          (float*)d_out, N, W, H, fx, fy);
}